// round 17
// baseline (speedup 1.0000x reference)
#include <cuda_runtime.h>
#include <cuda_bf16.h>
#include <math.h>
#include <stdint.h>

// Problem constants
#define NB   32
#define NPG0 128
#define NE   8192
#define EPG  (NE/NB)
#define CIN0 64
#define ED   32
#define HH   128
#define CED  33
#define NDB  34
#define YC   (CED*HH)     // 4224
#define K1   64
#define K2   32
#define K3   16
#define NN0  (NB*NPG0)

// ---------------- scratch ----------------
__device__ float g_y[NN0 * YC];
__device__ __nv_bfloat16 g_Ab[NN0 * 2 * HH];
__device__ __nv_bfloat16 g_Bb1[(NDB * HH) * 2 * CIN0];
__device__ __nv_bfloat16 g_Bb2[(NDB * HH) * 2 * HH];
__device__ __nv_bfloat16 g_Bb3[(NDB * HH) * 2 * HH];
__device__ float g_h2[NN0 * HH];
__device__ int   g_src[NE], g_dst[NE], g_valid[NE];
__device__ float g_partial[NB * 256];
__device__ int   g_ctr[4];

// ---------------- helpers ----------------
__device__ __forceinline__ void split2(float x, __nv_bfloat16& h1, __nv_bfloat16& h2) {
    h1 = __float2bfloat16(x);
    h2 = __float2bfloat16(x - __bfloat162float(h1));
}
__device__ __forceinline__ uint32_t smem_u32(const void* p) {
    return (uint32_t)__cvta_generic_to_shared(p);
}
__device__ __forceinline__ void cp_async16(uint32_t saddr, const void* gaddr) {
    asm volatile("cp.async.cg.shared.global [%0], [%1], 16;" :: "r"(saddr), "l"(gaddr));
}
__device__ __forceinline__ void ldsm4(uint32_t& r0, uint32_t& r1, uint32_t& r2, uint32_t& r3,
                                      uint32_t addr) {
    asm volatile("ldmatrix.sync.aligned.m8n8.x4.shared.b16 {%0,%1,%2,%3}, [%4];"
                 : "=r"(r0), "=r"(r1), "=r"(r2), "=r"(r3) : "r"(addr));
}
__device__ __forceinline__ void mma16816(float* c, const uint32_t* a, const uint32_t* b) {
    asm volatile("mma.sync.aligned.m16n8k16.row.col.f32.bf16.bf16.f32 "
                 "{%0,%1,%2,%3}, {%4,%5,%6,%7}, {%8,%9}, {%0,%1,%2,%3};"
                 : "+f"(c[0]), "+f"(c[1]), "+f"(c[2]), "+f"(c[3])
                 : "r"(a[0]), "r"(a[1]), "r"(a[2]), "r"(a[3]), "r"(b[0]), "r"(b[1]));
}

// ---------------- split_B element (shared by prep + gemm1 tail blocks) ----------------
__device__ __forceinline__ void split_B_elem(const float* __restrict__ W,
                                             const float* __restrict__ bvec,
                                             const float* __restrict__ root,
                                             __nv_bfloat16* __restrict__ Bb,
                                             int i, int cin) {
    int t = i / cin, k = i - t * cin;
    int d = t >> 7, o = t & 127;
    float w;
    if (d < ED)       w = W[(size_t)(d * cin + k) * HH + o];
    else if (d == ED) w = bvec[(size_t)k * HH + o];
    else              w = root[(size_t)k * HH + o];
    __nv_bfloat16 b1, b2;
    split2(w, b1, b2);
    __nv_bfloat16* row = Bb + (size_t)t * 2 * cin + k;
    row[0] = b1; row[cin] = b2;
}

// ---------------- critical prep: edges + split_A(layer1) + split_B(layer1 only) ----
#define PREP_SEG0 32      // edges
#define PREP_SEG1 1024    // split_A layer1
#define PREP_SEG2 1088    // split_B1
#define PREP_BLOCKS (PREP_SEG0 + PREP_SEG1 + PREP_SEG2)

__global__ void prep_k(const int* __restrict__ ei, const float* __restrict__ x,
                       __nv_bfloat16* __restrict__ Ab,
                       const float* __restrict__ nn1_w, const float* __restrict__ nn1_b,
                       const float* __restrict__ root1, __nv_bfloat16* __restrict__ Bb1,
                       int* __restrict__ src, int* __restrict__ dst,
                       int* __restrict__ valid) {
    int blk = blockIdx.x;
    if (blk < PREP_SEG0) {
        int e = blk * 256 + threadIdx.x;
        src[e] = ei[e]; dst[e] = ei[NE + e]; valid[e] = 1;
        return;
    }
    blk -= PREP_SEG0;
    if (blk < PREP_SEG1) {
        int i = blk * 256 + threadIdx.x;
        int r = i >> 6, k = i & 63;
        __nv_bfloat16 h1, h2;
        split2(x[i], h1, h2);
        __nv_bfloat16* row = Ab + (size_t)r * 2 * CIN0 + k;
        row[0] = h1; row[CIN0] = h2;
        return;
    }
    blk -= PREP_SEG1;
    split_B_elem(nn1_w, nn1_b, root1, Bb1, blk * 256 + threadIdx.x, CIN0);
}

// ---------------- raw mma.sync GEMM (R11 mainloop) + piggyback split_B tail blocks ----
#define SROW 72
#define STG  (128 * SROW)
#define GEMM_SMEM (3 * 2 * STG * 2)
#define BB_BLOCKS 2176    // per layer: 34*128*128 / 256

__global__ __launch_bounds__(256, 2)
void gemm_mma_k(const __nv_bfloat16* __restrict__ Ab, const __nv_bfloat16* __restrict__ Bb,
                float* __restrict__ Y, const float* __restrict__ bias,
                float* __restrict__ h2agg, int cin, int mrows,
                const float* __restrict__ w2s, const float* __restrict__ b2s,
                const float* __restrict__ r2s, __nv_bfloat16* __restrict__ Bb2o,
                const float* __restrict__ w3s, const float* __restrict__ b3s,
                const float* __restrict__ r3s, __nv_bfloat16* __restrict__ Bb3o) {
    // piggyback blocks: prep split_B for layers 2/3 during layer-1 GEMM
    if ((int)blockIdx.y >= mrows) {
        int lid = (blockIdx.y - mrows) * gridDim.x + blockIdx.x;   // 0..2*BB_BLOCKS-1
        if (lid < BB_BLOCKS)
            split_B_elem(w2s, b2s, r2s, Bb2o, lid * 256 + threadIdx.x, HH);
        else if (lid < 2 * BB_BLOCKS)
            split_B_elem(w3s, b3s, r3s, Bb3o, (lid - BB_BLOCKS) * 256 + threadIdx.x, HH);
        return;
    }

    extern __shared__ __nv_bfloat16 sm[];
    const int tid = threadIdx.x;
    const int lane = tid & 31;
    const int wid = tid >> 5;
    const int warp_m = wid & 3;
    const int warp_n = wid >> 2;
    const int mbase = blockIdx.y * 128;
    const int nbase = blockIdx.x * 128;
    const int Kp2 = 2 * cin;
    const int NPAIR = cin >> 6;
    const int NCH = NPAIR * 2;

    float acc[2][8][4];
#pragma unroll
    for (int i = 0; i < 2; i++)
#pragma unroll
        for (int j = 0; j < 8; j++)
#pragma unroll
            for (int q = 0; q < 4; q++) acc[i][j][q] = 0.f;

    auto prefetch = [&](int c) {
        const int s = c % 3;
        const int kc = (c & 1) * cin + ((c >> 1) << 6);
        __nv_bfloat16* base = sm + s * 2 * STG;
#pragma unroll
        for (int u = 0; u < 8; u++) {
            int q = tid + u * 256;
            int isB = q >> 10;
            int qq = q & 1023;
            int r = qq >> 3, ch = qq & 7;
            const __nv_bfloat16* g = isB
                ? (Bb + (size_t)(nbase + r) * Kp2 + kc + ch * 8)
                : (Ab + (size_t)(mbase + r) * Kp2 + kc + ch * 8);
            cp_async16(smem_u32(base + isB * STG + r * SROW + ch * 8), g);
        }
        asm volatile("cp.async.commit_group;" ::: "memory");
    };

    prefetch(0);
    prefetch(1);
    if (NCH > 2) prefetch(2);

    for (int p = 0; p < NPAIR; p++) {
        if (2 * p + 2 < NCH) asm volatile("cp.async.wait_group 1;" ::: "memory");
        else                 asm volatile("cp.async.wait_group 0;" ::: "memory");
        __syncthreads();

        const int sA = (2 * p) % 3, sB = (2 * p + 1) % 3;
        const uint32_t a1_base = smem_u32(sm + sA * 2 * STG);
        const uint32_t b1_base = a1_base + STG * 2;
        const uint32_t a2_base = smem_u32(sm + sB * 2 * STG);
        const uint32_t b2_base = a2_base + STG * 2;

        const int m8 = lane >> 3;
        const int arow_off = warp_m * 32 + (lane & 15);
        const int acol_sel = (lane >> 4) * 8;
        const int brow0 = warp_n * 64 + (m8 >> 1) * 8 + (lane & 7);
        const int bcol_sel = (m8 & 1) * 8;

#pragma unroll
        for (int kk = 0; kk < 4; kk++) {
            const uint32_t aoff = (uint32_t)(kk * 16 + acol_sel) * 2;
            const uint32_t boff = (uint32_t)(kk * 16 + bcol_sel) * 2;

            uint32_t af1[2][4];
#pragma unroll
            for (int i = 0; i < 2; i++)
                ldsm4(af1[i][0], af1[i][1], af1[i][2], af1[i][3],
                      a1_base + (uint32_t)((arow_off + i * 16) * SROW) * 2 + aoff);
            uint32_t bf1[8][2];
#pragma unroll
            for (int g = 0; g < 4; g++)
                ldsm4(bf1[2 * g][0], bf1[2 * g][1], bf1[2 * g + 1][0], bf1[2 * g + 1][1],
                      b1_base + (uint32_t)((brow0 + g * 16) * SROW) * 2 + boff);
#pragma unroll
            for (int i = 0; i < 2; i++)
#pragma unroll
                for (int j = 0; j < 8; j++)
                    mma16816(acc[i][j], af1[i], bf1[j]);

            uint32_t af2[2][4];
#pragma unroll
            for (int i = 0; i < 2; i++)
                ldsm4(af2[i][0], af2[i][1], af2[i][2], af2[i][3],
                      a2_base + (uint32_t)((arow_off + i * 16) * SROW) * 2 + aoff);
#pragma unroll
            for (int i = 0; i < 2; i++)
#pragma unroll
                for (int j = 0; j < 8; j++)
                    mma16816(acc[i][j], af2[i], bf1[j]);

            uint32_t bf2[8][2];
#pragma unroll
            for (int g = 0; g < 4; g++)
                ldsm4(bf2[2 * g][0], bf2[2 * g][1], bf2[2 * g + 1][0], bf2[2 * g + 1][1],
                      b2_base + (uint32_t)((brow0 + g * 16) * SROW) * 2 + boff);
#pragma unroll
            for (int i = 0; i < 2; i++)
#pragma unroll
                for (int j = 0; j < 8; j++)
                    mma16816(acc[i][j], af1[i], bf2[j]);
        }

        if (2 * p + 3 < NCH) {
            __syncthreads();
            prefetch(2 * p + 3);
        }
    }

    const int gid = lane >> 2, tig = lane & 3;
    if (blockIdx.x == 33) {
#pragma unroll
        for (int i = 0; i < 2; i++) {
            int row = mbase + warp_m * 32 + i * 16 + gid;
#pragma unroll
            for (int j = 0; j < 8; j++) {
                int col = warp_n * 64 + j * 8 + tig * 2;
                float b0 = bias[col], b1 = bias[col + 1];
                float* d0 = h2agg + (size_t)row * HH + col;
                d0[0] = acc[i][j][0] + b0;
                d0[1] = acc[i][j][1] + b1;
                float* d1 = h2agg + (size_t)(row + 8) * HH + col;
                d1[0] = acc[i][j][2] + b0;
                d1[1] = acc[i][j][3] + b1;
            }
        }
    } else {
#pragma unroll
        for (int i = 0; i < 2; i++) {
            int row = mbase + warp_m * 32 + i * 16 + gid;
#pragma unroll
            for (int j = 0; j < 8; j++) {
                int col = nbase + warp_n * 64 + j * 8 + tig * 2;
                *reinterpret_cast<float2*>(Y + (size_t)row * YC + col) =
                    make_float2(acc[i][j][0], acc[i][j][1]);
                *reinterpret_cast<float2*>(Y + (size_t)(row + 8) * YC + col) =
                    make_float2(acc[i][j][2], acc[i][j][3]);
            }
        }
    }
}

// ---------------- edge_msg: 2 warps per edge (d halves), 2 edges per 128-thr block ----
__global__ void edge_msg_k(const float* __restrict__ ea, const float* __restrict__ y,
                           float* __restrict__ agg, const int* __restrict__ src,
                           const int* __restrict__ dst, const int* __restrict__ valid) {
    int wid = threadIdx.x >> 5;
    int lane = threadIdx.x & 31;
    int e = blockIdx.x * 2 + (wid >> 1);
    int half = wid & 1;
    if (!valid[e]) return;
    float av = ea[(size_t)e * ED + lane];
    const float4* yr = reinterpret_cast<const float4*>(y + (size_t)src[e] * YC) + lane;
    float4 acc;
    if (half == 0) {
        float4 v = yr[ED * 32];     // bias slice, coeff 1
        acc = v;
    } else {
        acc = make_float4(0.f, 0.f, 0.f, 0.f);
    }
    int d0 = half * 16;
#pragma unroll
    for (int dd = 0; dd < 16; dd++) {
        int d = d0 + dd;
        float ad = __shfl_sync(0xffffffffu, av, d);
        float4 v = yr[d * 32];
        acc.x = fmaf(ad, v.x, acc.x);
        acc.y = fmaf(ad, v.y, acc.y);
        acc.z = fmaf(ad, v.z, acc.z);
        acc.w = fmaf(ad, v.w, acc.w);
    }
    float* ag = agg + (size_t)dst[e] * HH + lane * 4;
    atomicAdd(ag + 0, acc.x);
    atomicAdd(ag + 1, acc.y);
    atomicAdd(ag + 2, acc.z);
    atomicAdd(ag + 3, acc.w);
}

// ---------------- fused pool (R16 + busy-poll) ----------------
#define POOL_NT 512

__global__ __launch_bounds__(POOL_NT, 1)
void fused_pool_k(const float* __restrict__ h2, float* __restrict__ partial,
                  int* __restrict__ ctr,
                  const float* __restrict__ gamma, const float* __restrict__ beta,
                  const float* __restrict__ pw,
                  __nv_bfloat16* __restrict__ Ab,
                  int* __restrict__ src, int* __restrict__ dst,
                  int* __restrict__ valid,
                  int npg, int kk, int n, int last,
                  const float* __restrict__ w1, const float* __restrict__ b1,
                  const float* __restrict__ w2, const float* __restrict__ b2,
                  float* __restrict__ out) {
    extern __shared__ float fs[];
    float*  tile  = fs;
    float*  spw   = tile + npg * 132;
    float*  sc    = spw + 128;
    float*  gred  = sc + npg;
    float*  gred2 = gred + 2048;
    float*  bnsc  = gred2 + 2048;
    float*  bnbe  = bnsc + 128;
    float*  mlp1  = bnbe + 128;
    int*    rankA = (int*)(mlp1 + 64);

    float4* tile4  = reinterpret_cast<float4*>(tile);
    float4* gred4  = reinterpret_cast<float4*>(gred);
    float4* gred24 = reinterpret_cast<float4*>(gred2);
    const float4* spw4 = reinterpret_cast<const float4*>(spw);

    const int b = blockIdx.x;
    const int tid = threadIdx.x;
    const int lane = tid & 31;
    const int quad = tid & 31;
    const int rowg = tid >> 5;
    const int base = b * npg;

    float4 s4 = make_float4(0.f, 0.f, 0.f, 0.f);
    float4 q4 = make_float4(0.f, 0.f, 0.f, 0.f);
    for (int r = rowg; r < npg; r += 16) {
        float4 v = reinterpret_cast<const float4*>(h2)[(size_t)(base + r) * 32 + quad];
        tile4[r * 33 + quad] = v;
        s4.x += v.x; s4.y += v.y; s4.z += v.z; s4.w += v.w;
        q4.x = fmaf(v.x, v.x, q4.x); q4.y = fmaf(v.y, v.y, q4.y);
        q4.z = fmaf(v.z, v.z, q4.z); q4.w = fmaf(v.w, v.w, q4.w);
    }
    gred4[rowg * 32 + quad] = s4;
    gred24[rowg * 32 + quad] = q4;
    if (tid < 128) spw[tid] = pw[tid];
    __syncthreads();
    if (tid < 128) {
        float ss = 0.f, ss2 = 0.f;
#pragma unroll
        for (int g = 0; g < 16; g++) {
            ss  += gred[g * 128 + tid];
            ss2 += gred2[g * 128 + tid];
        }
        partial[b * 256 + tid] = ss;
        partial[b * 256 + 128 + tid] = ss2;
    }
    __threadfence();
    __syncthreads();
    if (tid == 0) {
        int old = atomicAdd(ctr, 1);
        int target = ((old >> 5) << 5) + 32;
        while (*(volatile int*)ctr < target) {}
    }
    __syncthreads();
    __threadfence();

    {
        int g = tid >> 7;
        int o128 = tid & 127;
        float S = 0.f, S2 = 0.f;
#pragma unroll
        for (int j = g * 8; j < g * 8 + 8; j++) {
            S  += __ldcg(&partial[j * 256 + o128]);
            S2 += __ldcg(&partial[j * 256 + 128 + o128]);
        }
        gred[g * 128 + o128] = S;
        gred2[g * 128 + o128] = S2;
    }
    __syncthreads();
    if (tid < 128) {
        float S  = gred[tid] + gred[128 + tid] + gred[256 + tid] + gred[384 + tid];
        float S2 = gred2[tid] + gred2[128 + tid] + gred2[256 + tid] + gred2[384 + tid];
        float inv_n = 1.f / (float)n;
        float mu = S * inv_n;
        float var = S2 * inv_n - mu * mu;
        float scal = gamma[tid] * rsqrtf(var + 1e-5f);
        bnsc[tid] = scal;
        bnbe[tid] = beta[tid] - scal * mu;
    }
    __syncthreads();

    float pwn;
    {
        float v = 0.f;
#pragma unroll
        for (int c = 0; c < 4; c++) {
            float p = spw[lane + c * 32];
            v = fmaf(p, p, v);
        }
#pragma unroll
        for (int st = 16; st > 0; st >>= 1)
            v += __shfl_xor_sync(0xffffffffu, v, st);
        pwn = sqrtf(v);
    }

    {
        float4 sc4 = reinterpret_cast<const float4*>(bnsc)[quad];
        float4 be4 = reinterpret_cast<const float4*>(bnbe)[quad];
        for (int r = rowg; r < npg; r += 16) {
            float4 v = tile4[r * 33 + quad];
            v.x = fmaxf(fmaf(sc4.x, v.x, be4.x), 0.f);
            v.y = fmaxf(fmaf(sc4.y, v.y, be4.y), 0.f);
            v.z = fmaxf(fmaf(sc4.z, v.z, be4.z), 0.f);
            v.w = fmaxf(fmaf(sc4.w, v.w, be4.w), 0.f);
            tile4[r * 33 + quad] = v;
        }
    }
    __syncthreads();

    const int tpn = POOL_NT / npg;
    const int node = tid / tpn;
    const int q = tid - node * tpn;
    const int q4n = (HH / tpn) >> 2;
    {
        float acc = 0.f;
        const float4* trow = tile4 + node * 33 + q * q4n;
        const float4* wrow = spw4 + q * q4n;
#pragma unroll 4
        for (int c = 0; c < q4n; c++) {
            float4 v = trow[c], w = wrow[c];
            acc = fmaf(v.x, w.x, acc); acc = fmaf(v.y, w.y, acc);
            acc = fmaf(v.z, w.z, acc); acc = fmaf(v.w, w.w, acc);
        }
        for (int st = tpn >> 1; st > 0; st >>= 1)
            acc += __shfl_xor_sync(0xffffffffu, acc, st);
        if (q == 0) sc[node] = tanhf(acc / pwn);
    }
    __syncthreads();

    {
        float mine = sc[node];
        int r = 0;
        for (int j = q; j < npg; j += tpn) {
            float sj = sc[j];
            r += (sj > mine) || (sj == mine && j < node);
        }
        for (int st = tpn >> 1; st > 0; st >>= 1)
            r += __shfl_xor_sync(0xffffffffu, r, st);
        if (q == 0) rankA[node] = r;
    }
    __syncthreads();

    if (!last) {
        for (int r = rowg; r < npg; r += 16) {
            int rk = rankA[r];
            if (rk < kk) {
                int nid = b * kk + rk;
                float scv = sc[r];
                float4 v = tile4[r * 33 + quad];
                v.x *= scv; v.y *= scv; v.z *= scv; v.w *= scv;
                __nv_bfloat16 a1[4], a2[4];
                split2(v.x, a1[0], a2[0]); split2(v.y, a1[1], a2[1]);
                split2(v.z, a1[2], a2[2]); split2(v.w, a1[3], a2[3]);
                __nv_bfloat16* row = Ab + (size_t)nid * 256;
                *reinterpret_cast<uint2*>(row + quad * 4) =
                    *reinterpret_cast<uint2*>(a1);
                *reinterpret_cast<uint2*>(row + 128 + quad * 4) =
                    *reinterpret_cast<uint2*>(a2);
            }
        }
        for (int e = b * EPG + tid; e < (b + 1) * EPG; e += POOL_NT) {
            if (valid[e]) {
                int rs = rankA[src[e] - base];
                int rd = rankA[dst[e] - base];
                if (rs < kk && rd < kk) { src[e] = b * kk + rs; dst[e] = b * kk + rd; }
                else valid[e] = 0;
            }
        }
    } else {
        float4 m4 = make_float4(0.f, 0.f, 0.f, 0.f);
        for (int r = rowg; r < npg; r += 16) {
            int rk = rankA[r];
            if (rk < kk) {
                float scv = sc[r];
                float4 v = tile4[r * 33 + quad];
                m4.x = fmaf(v.x, scv, m4.x); m4.y = fmaf(v.y, scv, m4.y);
                m4.z = fmaf(v.z, scv, m4.z); m4.w = fmaf(v.w, scv, m4.w);
            }
        }
        gred4[rowg * 32 + quad] = m4;
        __syncthreads();
        if (tid < 128) {
            float m = 0.f;
#pragma unroll
            for (int g = 0; g < 16; g++) m += gred[g * 128 + tid];
            spw[tid] = m * (1.f / (float)kk);
        }
        __syncthreads();
        int j = tid >> 3, q8 = tid & 7;
        float a = 0.f;
        for (int c = q8; c < HH; c += 8) a = fmaf(spw[c], w1[c * 64 + j], a);
#pragma unroll
        for (int st = 4; st > 0; st >>= 1)
            a += __shfl_xor_sync(0xffffffffu, a, st);
        if (q8 == 0) mlp1[j] = fmaxf(a + b1[j], 0.f) * w2[j];
        __syncthreads();
        if (tid < 32) {
            float v = mlp1[tid] + mlp1[tid + 32];
#pragma unroll
            for (int st = 16; st > 0; st >>= 1)
                v += __shfl_xor_sync(0xffffffffu, v, st);
            if (tid == 0) out[b] = 1.f / (1.f + expf(-(v + b2[0])));
        }
    }
}

// ---------------- host ----------------
static inline int pool_smem(int npg) {
    return (npg * 132 + 128 + npg + 2048 + 2048 + 128 + 128 + 64 + npg) * 4;
}

extern "C" void kernel_launch(void* const* d_in, const int* in_sizes, int n_in,
                              void* d_out, int out_size) {
    const float* x     = (const float*)d_in[0];
    const int*   ei    = (const int*)d_in[1];
    const float* ea    = (const float*)d_in[2];
    const float* nn1_w = (const float*)d_in[4];
    const float* nn1_b = (const float*)d_in[5];
    const float* root1 = (const float*)d_in[6];
    const float* bias1 = (const float*)d_in[7];
    const float* nn2_w = (const float*)d_in[8];
    const float* nn2_b = (const float*)d_in[9];
    const float* root2 = (const float*)d_in[10];
    const float* bias2 = (const float*)d_in[11];
    const float* nn3_w = (const float*)d_in[12];
    const float* nn3_b = (const float*)d_in[13];
    const float* root3 = (const float*)d_in[14];
    const float* bias3 = (const float*)d_in[15];
    const float* gamma1 = (const float*)d_in[16];
    const float* beta1  = (const float*)d_in[17];
    const float* gamma2 = (const float*)d_in[18];
    const float* beta2  = (const float*)d_in[19];
    const float* gamma3 = (const float*)d_in[20];
    const float* beta3  = (const float*)d_in[21];
    const float* pw1 = (const float*)d_in[22];
    const float* pw2 = (const float*)d_in[23];
    const float* pw3 = (const float*)d_in[24];
    const float* l1w = (const float*)d_in[25];
    const float* l1b = (const float*)d_in[26];
    const float* l2w = (const float*)d_in[27];
    const float* l2b = (const float*)d_in[28];
    float* out = (float*)d_out;

    float *yp, *h2p, *partp;
    __nv_bfloat16 *Abp, *Bb1p, *Bb2p, *Bb3p;
    int *srcp, *dstp, *validp, *ctrp;
    cudaGetSymbolAddress((void**)&yp, g_y);
    cudaGetSymbolAddress((void**)&Abp, g_Ab);
    cudaGetSymbolAddress((void**)&Bb1p, g_Bb1);
    cudaGetSymbolAddress((void**)&Bb2p, g_Bb2);
    cudaGetSymbolAddress((void**)&Bb3p, g_Bb3);
    cudaGetSymbolAddress((void**)&h2p, g_h2);
    cudaGetSymbolAddress((void**)&partp, g_partial);
    cudaGetSymbolAddress((void**)&srcp, g_src);
    cudaGetSymbolAddress((void**)&dstp, g_dst);
    cudaGetSymbolAddress((void**)&validp, g_valid);
    cudaGetSymbolAddress((void**)&ctrp, g_ctr);

    cudaFuncSetAttribute(gemm_mma_k, cudaFuncAttributeMaxDynamicSharedMemorySize, GEMM_SMEM);
    cudaFuncSetAttribute(fused_pool_k, cudaFuncAttributeMaxDynamicSharedMemorySize,
                         pool_smem(NPG0));

    // ---- critical prep (edges + Ab + Bb1 only) ----
    prep_k<<<PREP_BLOCKS, 256>>>(ei, x, Abp, nn1_w, nn1_b, root1, Bb1p,
                                 srcp, dstp, validp);

    // ---- layer 1 (+ piggyback Bb2/Bb3 prep in extra y-rows) ----
    const int extra_y = (2 * BB_BLOCKS + NDB - 1) / NDB;   // 128
    gemm_mma_k<<<dim3(NDB, NN0 / 128 + extra_y), 256, GEMM_SMEM>>>(
        Abp, Bb1p, yp, bias1, h2p, CIN0, NN0 / 128,
        nn2_w, nn2_b, root2, Bb2p, nn3_w, nn3_b, root3, Bb3p);
    edge_msg_k<<<NE / 2, 128>>>(ea, yp, h2p, srcp, dstp, validp);
    fused_pool_k<<<NB, POOL_NT, pool_smem(NPG0)>>>(
        h2p, partp, ctrp + 0, gamma1, beta1, pw1, Abp, srcp, dstp, validp,
        NPG0, K1, NN0, 0, nullptr, nullptr, nullptr, nullptr, nullptr);

    // ---- layer 2 ----
    int n2 = NB * K1;
    gemm_mma_k<<<dim3(NDB, n2 / 128), 256, GEMM_SMEM>>>(
        Abp, Bb2p, yp, bias2, h2p, HH, n2 / 128,
        nullptr, nullptr, nullptr, nullptr, nullptr, nullptr, nullptr, nullptr);
    edge_msg_k<<<NE / 2, 128>>>(ea, yp, h2p, srcp, dstp, validp);
    fused_pool_k<<<NB, POOL_NT, pool_smem(K1)>>>(
        h2p, partp, ctrp + 1, gamma2, beta2, pw2, Abp, srcp, dstp, validp,
        K1, K2, n2, 0, nullptr, nullptr, nullptr, nullptr, nullptr);

    // ---- layer 3 + fused readout ----
    int n3 = NB * K2;
    gemm_mma_k<<<dim3(NDB, n3 / 128), 256, GEMM_SMEM>>>(
        Abp, Bb3p, yp, bias3, h2p, HH, n3 / 128,
        nullptr, nullptr, nullptr, nullptr, nullptr, nullptr, nullptr, nullptr);
    edge_msg_k<<<NE / 2, 128>>>(ea, yp, h2p, srcp, dstp, validp);
    fused_pool_k<<<NB, POOL_NT, pool_smem(K2)>>>(
        h2p, partp, ctrp + 2, gamma3, beta3, pw3, Abp, srcp, dstp, validp,
        K2, K3, n3, 1, l1w, l1b, l2w, l2b, out);
}